// round 7
// baseline (speedup 1.0000x reference)
#include <cuda_runtime.h>
#include <cuda_bf16.h>
#include <math.h>
#include <stdint.h>

// Problem dims
#define Tn 512
#define Bn 64
#define In 512
#define Hn 1024
#define On 512
#define Gn 4096
#define TBn (Tn*Bn)           // 32768

// Persistent recurrence config (R2-proven shape)
#define NCTA 128
#define NTHR 256
#define HT   128
#define HTS  132
#define GSM_S 34

// HMMA GEMM tile config
#define BM 128
#define BN 128
#define BK 32
#define ROWB 80                    // smem row stride bytes (32 bf16 + 8 pad)
#define MATB (128*ROWB)            // 10240 B per matrix tile
#define STGB (4*MATB)              // 40960 B per stage (Ahi,Alo,Whi,Wlo)
#define SMEM_GEMM (2*STGB)         // 81920 B

// Scratch (device globals)
__device__ float g_pre[(size_t)TBn * Gn];
__device__ float g_hseq[(size_t)TBn * Hn];
__device__ float g_h[Bn * Hn];
__device__ unsigned g_arrive[NCTA] = {};
__device__ unsigned g_bar_gen = 0;
__device__ __nv_bfloat16 g_ahi[(size_t)TBn * Hn];
__device__ __nv_bfloat16 g_alo[(size_t)TBn * Hn];
__device__ __nv_bfloat16 g_whi[(size_t)Gn * Hn];
__device__ __nv_bfloat16 g_wlo[(size_t)Gn * Hn];

typedef unsigned long long u64;

__device__ __forceinline__ void ffma2(u64& d, u64 a, u64 b) {
    asm("fma.rn.f32x2 %0, %1, %2, %0;" : "+l"(d) : "l"(a), "l"(b));
}
__device__ __forceinline__ float2 unpack2(u64 v) {
    float2 r; asm("mov.b64 {%0, %1}, %2;" : "=f"(r.x), "=f"(r.y) : "l"(v)); return r;
}
__device__ __forceinline__ u64 d2u(double d) { return __double_as_longlong(d); }
__device__ __forceinline__ float sigf(float x) { return 1.0f / (1.0f + expf(-x)); }

__device__ __forceinline__ uint32_t smem_u32(const void* p) {
    uint32_t a;
    asm("{ .reg .u64 t; cvta.to.shared.u64 t, %1; cvt.u32.u64 %0, t; }"
        : "=r"(a) : "l"(p));
    return a;
}
__device__ __forceinline__ void cpasync16(uint32_t dst, const void* src) {
    asm volatile("cp.async.cg.shared.global [%0], [%1], 16;"
                 :: "r"(dst), "l"(src) : "memory");
}
__device__ __forceinline__ void cp_commit() {
    asm volatile("cp.async.commit_group;" ::: "memory");
}
__device__ __forceinline__ void ldsm4(uint32_t& r0, uint32_t& r1, uint32_t& r2,
                                      uint32_t& r3, uint32_t addr) {
    asm volatile("ldmatrix.sync.aligned.m8n8.x4.shared.b16 {%0,%1,%2,%3}, [%4];"
                 : "=r"(r0), "=r"(r1), "=r"(r2), "=r"(r3) : "r"(addr));
}
__device__ __forceinline__ void mma16816(float* c, uint32_t a0, uint32_t a1,
                                         uint32_t a2, uint32_t a3,
                                         uint32_t b0, uint32_t b1) {
    asm volatile(
        "mma.sync.aligned.m16n8k16.row.col.f32.bf16.bf16.f32 "
        "{%0,%1,%2,%3}, {%4,%5,%6,%7}, {%8,%9}, {%0,%1,%2,%3};"
        : "+f"(c[0]), "+f"(c[1]), "+f"(c[2]), "+f"(c[3])
        : "r"(a0), "r"(a1), "r"(a2), "r"(a3), "r"(b0), "r"(b1));
}

// ---------------- grid barrier (replay-safe monotonic phases) --------------
__device__ __forceinline__ void grid_sync(unsigned phase) {
    __syncthreads();
    if (threadIdx.x == 0) {
        __threadfence();
        asm volatile("st.release.gpu.global.u32 [%0], %1;"
                     :: "l"(&g_arrive[blockIdx.x]), "r"(phase) : "memory");
    }
    if (blockIdx.x == 0) {
        if (threadIdx.x < NCTA) {
            unsigned v;
            do {
                asm volatile("ld.acquire.gpu.global.u32 %0, [%1];"
                             : "=r"(v) : "l"(&g_arrive[threadIdx.x]));
            } while (v != phase);
        }
        __syncthreads();
        if (threadIdx.x == 0) {
            __threadfence();
            asm volatile("st.release.gpu.global.u32 [%0], %1;"
                         :: "l"(&g_bar_gen), "r"(phase) : "memory");
        }
    } else if (threadIdx.x == 0) {
        unsigned v;
        do {
            asm volatile("ld.acquire.gpu.global.u32 %0, [%1];"
                         : "=r"(v) : "l"(&g_bar_gen));
        } while (v != phase);
    }
    __syncthreads();
}

// ---------------------------------------------------------------------------
// Persistent LSTM layer (R2-proven 256-thread version)
// ---------------------------------------------------------------------------
__global__ void __launch_bounds__(NTHR, 1)
lstm_recur(const float* __restrict__ Whh, const float* __restrict__ pre,
           float* __restrict__ hseq)
{
    extern __shared__ float smem[];
    float4* Wsm = (float4*)smem;              // [256 kg][32 r] float4 = 128 KB
    float*  h_s = smem + 32768;               // [64][HTS]
    float*  gsm = h_s;                        // [64][GSM_S]

    const int tid = threadIdx.x;
    const int cta = blockIdx.x;
    const int j0  = cta * 8;
    const int tx  = tid & 15;
    const int ty  = tid >> 4;

    unsigned phase0;
    asm volatile("ld.acquire.gpu.global.u32 %0, [%1];" : "=r"(phase0) : "l"(&g_bar_gen));

    for (int l = 0; l < 32; l++) {
        int r  = l;
        int kg = tid;
        int grow = (r >> 3) * Hn + j0 + (r & 7);
        Wsm[kg * 32 + r] = *(const float4*)(Whh + (size_t)grow * Hn + kg * 4);
    }

    const int pb = tid >> 2;
    const int jj = (tid & 3) * 2;
    float c0 = 0.0f, c1 = 0.0f;

    for (int t = 0; t < Tn; t++) {
        u64 acc[4][2];
#pragma unroll
        for (int i = 0; i < 4; i++) { acc[i][0] = 0ULL; acc[i][1] = 0ULL; }

        float4 hreg[8];
#pragma unroll
        for (int l = 0; l < 8; l++) {
            int f = tid + l * NTHR;
            hreg[l] = __ldg((const float4*)(g_h + (size_t)(f >> 5) * Hn + (f & 31) * 4));
        }

        for (int kt = 0; kt < Hn / HT; kt++) {
#pragma unroll
            for (int l = 0; l < 8; l++) {
                int f = tid + l * NTHR;
                *(float4*)(h_s + (f >> 5) * HTS + (f & 31) * 4) = hreg[l];
            }
            __syncthreads();
            if (kt + 1 < Hn / HT) {
#pragma unroll
                for (int l = 0; l < 8; l++) {
                    int f = tid + l * NTHR;
                    hreg[l] = __ldg((const float4*)(g_h + (size_t)(f >> 5) * Hn
                                                    + (kt + 1) * HT + (f & 31) * 4));
                }
            }
#pragma unroll 4
            for (int kc = 0; kc < HT / 4; kc++) {
                int kg = kt * (HT / 4) + kc;
                double2 w0 = *(const double2*)(Wsm + kg * 32 + 2 * tx);
                double2 w1 = *(const double2*)(Wsm + kg * 32 + 2 * tx + 1);
                u64 w0a = d2u(w0.x), w0b = d2u(w0.y);
                u64 w1a = d2u(w1.x), w1b = d2u(w1.y);
#pragma unroll
                for (int i = 0; i < 4; i++) {
                    double2 hv = *(const double2*)(h_s + (4 * ty + i) * HTS + kc * 4);
                    u64 ha = d2u(hv.x), hb = d2u(hv.y);
                    ffma2(acc[i][0], ha, w0a); ffma2(acc[i][0], hb, w0b);
                    ffma2(acc[i][1], ha, w1a); ffma2(acc[i][1], hb, w1b);
                }
            }
            __syncthreads();
        }

#pragma unroll
        for (int i = 0; i < 4; i++) {
            int b = 4 * ty + i;
            float2 v0 = unpack2(acc[i][0]);
            float2 v1 = unpack2(acc[i][1]);
            *(float2*)(gsm + b * GSM_S + 2 * tx) = make_float2(v0.x + v0.y, v1.x + v1.y);
        }
        __syncthreads();

        {
            const float* gb = gsm + pb * GSM_S;
            float2 ri = *(const float2*)(gb + jj);
            float2 rf = *(const float2*)(gb + 8 + jj);
            float2 rg = *(const float2*)(gb + 16 + jj);
            float2 ro = *(const float2*)(gb + 24 + jj);
            size_t pbase = (size_t)t * ((size_t)Bn * Gn) + (size_t)pb * Gn + j0 + jj;
            float2 qi = *(const float2*)(pre + pbase);
            float2 qf = *(const float2*)(pre + pbase + Hn);
            float2 qg = *(const float2*)(pre + pbase + 2 * Hn);
            float2 qo = *(const float2*)(pre + pbase + 3 * Hn);

            float i0 = sigf(ri.x + qi.x), i1 = sigf(ri.y + qi.y);
            float f0 = sigf(rf.x + qf.x), f1 = sigf(rf.y + qf.y);
            float g0 = tanhf(rg.x + qg.x), g1 = tanhf(rg.y + qg.y);
            float o0 = sigf(ro.x + qo.x), o1 = sigf(ro.y + qo.y);
            c0 = f0 * c0 + i0 * g0;
            c1 = f1 * c1 + i1 * g1;
            float h0 = o0 * tanhf(c0);
            float h1 = o1 * tanhf(c1);

            int hidx = pb * Hn + j0 + jj;
            *(float2*)(g_h + hidx) = make_float2(h0, h1);
            *(float2*)(hseq + (size_t)t * Bn * Hn + hidx) = make_float2(h0, h1);
        }

        grid_sync(phase0 + t + 1);
    }
}

// ---------------------------------------------------------------------------
// fp32 -> bf16 hi/lo split conversion (elementwise)
// ---------------------------------------------------------------------------
__global__ void cvt_split(const float* __restrict__ in,
                          __nv_bfloat16* __restrict__ hi,
                          __nv_bfloat16* __restrict__ lo, int n4)
{
    int i = blockIdx.x * blockDim.x + threadIdx.x;
    if (i >= n4) return;
    float4 v = __ldg((const float4*)in + i);
    __nv_bfloat16 h0 = __float2bfloat16(v.x);
    __nv_bfloat16 h1 = __float2bfloat16(v.y);
    __nv_bfloat16 h2 = __float2bfloat16(v.z);
    __nv_bfloat16 h3 = __float2bfloat16(v.w);
    __nv_bfloat16 l0 = __float2bfloat16(v.x - __bfloat162float(h0));
    __nv_bfloat16 l1 = __float2bfloat16(v.y - __bfloat162float(h1));
    __nv_bfloat16 l2 = __float2bfloat16(v.z - __bfloat162float(h2));
    __nv_bfloat16 l3 = __float2bfloat16(v.w - __bfloat162float(h3));
    *((__nv_bfloat162*)hi + 2*i)     = __nv_bfloat162(h0, h1);
    *((__nv_bfloat162*)hi + 2*i + 1) = __nv_bfloat162(h2, h3);
    *((__nv_bfloat162*)lo + 2*i)     = __nv_bfloat162(l0, l1);
    *((__nv_bfloat162*)lo + 2*i + 1) = __nv_bfloat162(l2, l3);
}

// ---------------------------------------------------------------------------
// HMMA bf16-split GEMM: C[M,N] = (Ahi+Alo)[M,K] @ (Whi+Wlo)[N,K]^T + bias
// 3 products: Ahi*Whi + Ahi*Wlo + Alo*Whi, fp32 accumulate.
// CTA 128x128, BK=32, 8 warps (warp tile 64x32), cp.async double buffering.
// ---------------------------------------------------------------------------
__global__ void __launch_bounds__(256, 1)
gemm_tc(const __nv_bfloat16* __restrict__ Ahi, const __nv_bfloat16* __restrict__ Alo,
        const __nv_bfloat16* __restrict__ Whi, const __nv_bfloat16* __restrict__ Wlo,
        const float* __restrict__ b0, const float* __restrict__ b1,
        float* __restrict__ C, int K, int N)
{
    extern __shared__ char smc[];
    const uint32_t sb = smem_u32(smc);
    const int tid = threadIdx.x, lane = tid & 31, wid = tid >> 5;
    const int m0 = blockIdx.y * BM, n0 = blockIdx.x * BN;
    const int wm = (wid & 1) * 64, wn = (wid >> 1) * 32;

    float acc[4][4][4];
#pragma unroll
    for (int i = 0; i < 4; i++)
#pragma unroll
        for (int j = 0; j < 4; j++)
#pragma unroll
            for (int l = 0; l < 4; l++) acc[i][j][l] = 0.0f;

    // Loader chunk mapping: chunk c in {tid, tid+256}; row=c>>2, ch=c&3
    const int r0l = tid >> 2, ch0 = (tid & 3);            // chunk tid
    const int r1l = (tid + 256) >> 2, ch1 = ((tid + 256) & 3);

    const int NS = K / BK;

    // ---- stage loader (cp.async) ----
    auto load_stage = [&](int st, int ck) {
        uint32_t sbase = sb + st * STGB;
        const __nv_bfloat16* ap;
        // Ahi / Alo
        ap = Ahi + (size_t)(m0 + r0l) * K + ck * BK + ch0 * 8;
        cpasync16(sbase + 0*MATB + r0l * ROWB + ch0 * 16, ap);
        ap = Ahi + (size_t)(m0 + r1l) * K + ck * BK + ch1 * 8;
        cpasync16(sbase + 0*MATB + r1l * ROWB + ch1 * 16, ap);
        ap = Alo + (size_t)(m0 + r0l) * K + ck * BK + ch0 * 8;
        cpasync16(sbase + 1*MATB + r0l * ROWB + ch0 * 16, ap);
        ap = Alo + (size_t)(m0 + r1l) * K + ck * BK + ch1 * 8;
        cpasync16(sbase + 1*MATB + r1l * ROWB + ch1 * 16, ap);
        // Whi / Wlo
        ap = Whi + (size_t)(n0 + r0l) * K + ck * BK + ch0 * 8;
        cpasync16(sbase + 2*MATB + r0l * ROWB + ch0 * 16, ap);
        ap = Whi + (size_t)(n0 + r1l) * K + ck * BK + ch1 * 8;
        cpasync16(sbase + 2*MATB + r1l * ROWB + ch1 * 16, ap);
        ap = Wlo + (size_t)(n0 + r0l) * K + ck * BK + ch0 * 8;
        cpasync16(sbase + 3*MATB + r0l * ROWB + ch0 * 16, ap);
        ap = Wlo + (size_t)(n0 + r1l) * K + ck * BK + ch1 * 8;
        cpasync16(sbase + 3*MATB + r1l * ROWB + ch1 * 16, ap);
        cp_commit();
    };

    load_stage(0, 0);

    // ldmatrix lane address components (byte offsets within a matrix tile)
    const uint32_t aoff = (uint32_t)((wm + (lane & 15)) * ROWB + (lane >> 4) * 16);
    const uint32_t boff = (uint32_t)((wn + (lane & 7) + ((lane >> 4) << 3)) * ROWB
                                     + ((lane >> 3) & 1) * 16);

    for (int ck = 0; ck < NS; ck++) {
        const int st = ck & 1;
        if (ck + 1 < NS) {
            load_stage(st ^ 1, ck + 1);
            asm volatile("cp.async.wait_group 1;" ::: "memory");
        } else {
            asm volatile("cp.async.wait_group 0;" ::: "memory");
        }
        __syncthreads();

        const uint32_t sbase = sb + st * STGB;
#pragma unroll
        for (int kk = 0; kk < 2; kk++) {
            const uint32_t ko = kk * 32;
            // B frags: nb 0..1, hi & lo
            uint32_t bh[2][4], bl[2][4];
#pragma unroll
            for (int nb = 0; nb < 2; nb++) {
                uint32_t ba = sbase + boff + nb * (16 * ROWB) + ko;
                ldsm4(bh[nb][0], bh[nb][1], bh[nb][2], bh[nb][3], ba + 2*MATB);
                ldsm4(bl[nb][0], bl[nb][1], bl[nb][2], bl[nb][3], ba + 3*MATB);
            }
            // A frags: mi 0..3, hi & lo
            uint32_t ah[4][4], al[4][4];
#pragma unroll
            for (int mi = 0; mi < 4; mi++) {
                uint32_t aa = sbase + aoff + mi * (16 * ROWB) + ko;
                ldsm4(ah[mi][0], ah[mi][1], ah[mi][2], ah[mi][3], aa);
                ldsm4(al[mi][0], al[mi][1], al[mi][2], al[mi][3], aa + MATB);
            }
#pragma unroll
            for (int mi = 0; mi < 4; mi++) {
#pragma unroll
                for (int ni = 0; ni < 4; ni++) {
                    const int nb = ni >> 1, pr = (ni & 1) * 2;
                    float* c = acc[mi][ni];
                    mma16816(c, ah[mi][0], ah[mi][1], ah[mi][2], ah[mi][3],
                             bh[nb][pr], bh[nb][pr + 1]);
                    mma16816(c, ah[mi][0], ah[mi][1], ah[mi][2], ah[mi][3],
                             bl[nb][pr], bl[nb][pr + 1]);
                    mma16816(c, al[mi][0], al[mi][1], al[mi][2], al[mi][3],
                             bh[nb][pr], bh[nb][pr + 1]);
                }
            }
        }
        __syncthreads();
    }

    // Epilogue: fragments -> global with bias
#pragma unroll
    for (int ni = 0; ni < 4; ni++) {
        int cc = n0 + wn + ni * 8 + (lane & 3) * 2;
        float bb0 = __ldg(b0 + cc) + (b1 ? __ldg(b1 + cc) : 0.0f);
        float bb1 = __ldg(b0 + cc + 1) + (b1 ? __ldg(b1 + cc + 1) : 0.0f);
#pragma unroll
        for (int mi = 0; mi < 4; mi++) {
            int rr = m0 + wm + mi * 16 + (lane >> 2);
            float* c = acc[mi][ni];
            *(float2*)(C + (size_t)rr * N + cc) =
                make_float2(c[0] + bb0, c[1] + bb1);
            *(float2*)(C + (size_t)(rr + 8) * N + cc) =
                make_float2(c[2] + bb0, c[3] + bb1);
        }
    }
}

// ---------------------------------------------------------------------------
extern "C" void kernel_launch(void* const* d_in, const int* in_sizes, int n_in,
                              void* d_out, int out_size)
{
    const float* x    = (const float*)d_in[0];
    const float* Wih0 = (const float*)d_in[1];
    const float* Whh0 = (const float*)d_in[2];
    const float* bih0 = (const float*)d_in[3];
    const float* bhh0 = (const float*)d_in[4];
    const float* Wih1 = (const float*)d_in[5];
    const float* Whh1 = (const float*)d_in[6];
    const float* bih1 = (const float*)d_in[7];
    const float* bhh1 = (const float*)d_in[8];
    const float* Wout = (const float*)d_in[9];
    const float* bout = (const float*)d_in[10];
    float* out = (float*)d_out;

    float *pre, *hs, *h;
    __nv_bfloat16 *ahi, *alo, *whi, *wlo;
    cudaGetSymbolAddress((void**)&pre, g_pre);
    cudaGetSymbolAddress((void**)&hs,  g_hseq);
    cudaGetSymbolAddress((void**)&h,   g_h);
    cudaGetSymbolAddress((void**)&ahi, g_ahi);
    cudaGetSymbolAddress((void**)&alo, g_alo);
    cudaGetSymbolAddress((void**)&whi, g_whi);
    cudaGetSymbolAddress((void**)&wlo, g_wlo);

    const int SMEM_RECUR = 131072 + 64 * HTS * 4;
    cudaFuncSetAttribute(lstm_recur, cudaFuncAttributeMaxDynamicSharedMemorySize,
                         SMEM_RECUR);
    cudaFuncSetAttribute(gemm_tc, cudaFuncAttributeMaxDynamicSharedMemorySize,
                         SMEM_GEMM);

    // ---- Layer 0 pre-GEMM (HMMA bf16 split) ----
    cvt_split<<<(TBn*In/4 + 255)/256, 256>>>(x, ahi, alo, TBn*In/4);
    cvt_split<<<(Gn*In/4 + 255)/256, 256>>>(Wih0, whi, wlo, Gn*In/4);
    gemm_tc<<<dim3(Gn/BN, TBn/BM), 256, SMEM_GEMM>>>(
        ahi, alo, whi, wlo, bih0, bhh0, pre, In, Gn);
    cudaMemsetAsync(h, 0, sizeof(float)*Bn*Hn);
    lstm_recur<<<NCTA, NTHR, SMEM_RECUR>>>(Whh0, pre, hs);

    // ---- Layer 1 pre-GEMM ----
    cvt_split<<<(TBn*Hn/4 + 255)/256, 256>>>(hs, ahi, alo, TBn*Hn/4);
    cvt_split<<<(Gn*Hn/4 + 255)/256, 256>>>(Wih1, whi, wlo, Gn*Hn/4);
    gemm_tc<<<dim3(Gn/BN, TBn/BM), 256, SMEM_GEMM>>>(
        ahi, alo, whi, wlo, bih1, bhh1, pre, Hn, Gn);
    cudaMemsetAsync(h, 0, sizeof(float)*Bn*Hn);
    lstm_recur<<<NCTA, NTHR, SMEM_RECUR>>>(Whh1, pre, hs);

    // ---- Output projection ----
    cvt_split<<<(TBn*Hn/4 + 255)/256, 256>>>(hs, ahi, alo, TBn*Hn/4);
    cvt_split<<<(On*Hn/4 + 255)/256, 256>>>(Wout, whi, wlo, On*Hn/4);
    gemm_tc<<<dim3(On/BN, TBn/BM), 256, SMEM_GEMM>>>(
        ahi, alo, whi, wlo, bout, nullptr, out, Hn, On);
}

// round 9
// speedup vs baseline: 2.2400x; 2.2400x over previous
#include <cuda_runtime.h>
#include <cuda_bf16.h>
#include <math.h>
#include <stdint.h>

// Problem dims
#define Tn 512
#define Bn 64
#define In 512
#define Hn 1024
#define On 512
#define Gn 4096
#define TBn (Tn*Bn)           // 32768

#define NCTA 128
#define NTHR 256

// ---- recurrence smem layout (bytes) ----
#define RWS 2064                       // W row stride (1024 bf16 + 16B pad)
#define W_LO_OFF (32*RWS)              // 66048
#define A_OFF    (2*32*RWS)            // 132096
#define A_STRIDE 144                   // 64 k-bf16 (128B) + 16B pad
#define A_MAT    (64*A_STRIDE)         // 9216
#define A_STAGE  (2*A_MAT)             // hi+lo = 18432
#define NSTG 4
#define GSM_OFF  (A_OFF + NSTG*A_STAGE)  // 205824
#define GSTR 34                        // EVEN stride: float2 stores stay 8B-aligned
#define SMEM_RECUR (GSM_OFF + 64*GSTR*4) // 214528

// ---- HMMA GEMM tile config (R7-proven) ----
#define BM 128
#define BN 128
#define BK 32
#define ROWB 80
#define MATB (128*ROWB)
#define STGB (4*MATB)
#define SMEM_GEMM (2*STGB)

// Scratch (device globals)
__device__ float g_pre[(size_t)TBn * Gn];
__device__ float g_c[Bn * Hn];
__device__ unsigned g_arrive[NCTA] = {};
__device__ unsigned g_bar_gen = 0;
__device__ __nv_bfloat16 g_hhi[Bn * Hn];
__device__ __nv_bfloat16 g_hlo[Bn * Hn];
__device__ __nv_bfloat16 g_shi[(size_t)TBn * Hn];   // hseq hi (GEMM A input)
__device__ __nv_bfloat16 g_slo[(size_t)TBn * Hn];   // hseq lo
__device__ __nv_bfloat16 g_ahi[(size_t)TBn * Hn];   // x split
__device__ __nv_bfloat16 g_alo[(size_t)TBn * Hn];
__device__ __nv_bfloat16 g_whi[(size_t)Gn * Hn];
__device__ __nv_bfloat16 g_wlo[(size_t)Gn * Hn];

__device__ __forceinline__ float sigf(float x) { return 1.0f / (1.0f + expf(-x)); }

__device__ __forceinline__ uint32_t smem_u32(const void* p) {
    uint32_t a;
    asm("{ .reg .u64 t; cvta.to.shared.u64 t, %1; cvt.u32.u64 %0, t; }"
        : "=r"(a) : "l"(p));
    return a;
}
__device__ __forceinline__ void cpasync16(uint32_t dst, const void* src) {
    asm volatile("cp.async.cg.shared.global [%0], [%1], 16;"
                 :: "r"(dst), "l"(src) : "memory");
}
__device__ __forceinline__ void cp_commit() {
    asm volatile("cp.async.commit_group;" ::: "memory");
}
__device__ __forceinline__ void ldsm4(uint32_t& r0, uint32_t& r1, uint32_t& r2,
                                      uint32_t& r3, uint32_t addr) {
    asm volatile("ldmatrix.sync.aligned.m8n8.x4.shared.b16 {%0,%1,%2,%3}, [%4];"
                 : "=r"(r0), "=r"(r1), "=r"(r2), "=r"(r3) : "r"(addr));
}
__device__ __forceinline__ void mma16816(float* c, uint32_t a0, uint32_t a1,
                                         uint32_t a2, uint32_t a3,
                                         uint32_t b0, uint32_t b1) {
    asm volatile(
        "mma.sync.aligned.m16n8k16.row.col.f32.bf16.bf16.f32 "
        "{%0,%1,%2,%3}, {%4,%5,%6,%7}, {%8,%9}, {%0,%1,%2,%3};"
        : "+f"(c[0]), "+f"(c[1]), "+f"(c[2]), "+f"(c[3])
        : "r"(a0), "r"(a1), "r"(a2), "r"(a3), "r"(b0), "r"(b1));
}

// ---------------- grid barrier (replay-safe monotonic phases) --------------
__device__ __forceinline__ void grid_sync(unsigned phase) {
    __syncthreads();
    if (threadIdx.x == 0) {
        __threadfence();
        asm volatile("st.release.gpu.global.u32 [%0], %1;"
                     :: "l"(&g_arrive[blockIdx.x]), "r"(phase) : "memory");
    }
    if (blockIdx.x == 0) {
        if (threadIdx.x < NCTA) {
            unsigned v;
            do {
                asm volatile("ld.acquire.gpu.global.u32 %0, [%1];"
                             : "=r"(v) : "l"(&g_arrive[threadIdx.x]));
            } while (v != phase);
        }
        __syncthreads();
        if (threadIdx.x == 0) {
            __threadfence();
            asm volatile("st.release.gpu.global.u32 [%0], %1;"
                         :: "l"(&g_bar_gen), "r"(phase) : "memory");
        }
    } else if (threadIdx.x == 0) {
        unsigned v;
        do {
            asm volatile("ld.acquire.gpu.global.u32 %0, [%1];"
                         : "=r"(v) : "l"(&g_bar_gen));
        } while (v != phase);
    }
    __syncthreads();
}

// ---------------------------------------------------------------------------
// Persistent HMMA LSTM layer. CTA owns 32 W_hh rows (4 gates x 8 j-cols),
// bf16 hi/lo in SMEM. h carried globally as bf16 hi/lo. Per step:
// gates[64x32] = h @ Wslice^T via mma (3-product split), then pointwise.
// ---------------------------------------------------------------------------
__global__ void __launch_bounds__(NTHR, 1)
lstm_recur(const float* __restrict__ Whh, const float* __restrict__ pre,
           __nv_bfloat16* __restrict__ shi, __nv_bfloat16* __restrict__ slo)
{
    extern __shared__ char smc[];
    const uint32_t sb = smem_u32(smc);
    const int tid = threadIdx.x;
    const int lane = tid & 31, wid = tid >> 5;
    const int mi = wid & 3, nz = wid >> 2;
    const int cta = blockIdx.x;
    const int j0  = cta * 8;

    unsigned phase0;
    asm volatile("ld.acquire.gpu.global.u32 %0, [%1];" : "=r"(phase0) : "l"(&g_bar_gen));

    // ---- Load & split W slice into SMEM (once per layer) ----
    for (int l = 0; l < 128; l++) {
        int f = tid + l * NTHR;          // 0..32767
        int r = f >> 10, k = f & 1023;
        float v = __ldg(Whh + (size_t)((r >> 3) * Hn + j0 + (r & 7)) * Hn + k);
        __nv_bfloat16 h = __float2bfloat16(v);
        __nv_bfloat16 lo = __float2bfloat16(v - __bfloat162float(h));
        *(__nv_bfloat16*)(smc + r * RWS + k * 2) = h;
        *(__nv_bfloat16*)(smc + W_LO_OFF + r * RWS + k * 2) = lo;
    }
    __syncthreads();

    // ldmatrix address templates
    const uint32_t a_lane = (uint32_t)((mi * 16 + (lane & 15)) * A_STRIDE
                                       + (lane >> 4) * 16);
    const uint32_t b_lane = (uint32_t)((nz * 16 + (lane & 7) + ((lane >> 4) << 3)) * RWS
                                       + ((lane >> 3) & 1) * 16);

    const int pb = tid >> 2;              // pointwise batch
    const int jj = (tid & 3) * 2;         // pointwise j-pair
    float* cp0 = g_c + pb * Hn + j0 + jj;

    for (int t = 0; t < Tn; t++) {
        // early-issue pre loads
        size_t pbase = (size_t)t * ((size_t)Bn * Gn) + (size_t)pb * Gn + j0 + jj;
        float2 qi = *(const float2*)(pre + pbase);
        float2 qf = *(const float2*)(pre + pbase + Hn);
        float2 qg = *(const float2*)(pre + pbase + 2 * Hn);
        float2 qo = *(const float2*)(pre + pbase + 3 * Hn);

        float acc[2][4];
#pragma unroll
        for (int n = 0; n < 2; n++)
#pragma unroll
            for (int i = 0; i < 4; i++) acc[n][i] = 0.0f;

        // stage loader lambda
        auto load_stage = [&](int st, int ck) {
#pragma unroll
            for (int l = 0; l < 4; l++) {
                int idx = tid + l * NTHR;
                int sel = idx >> 9;
                int i = idx & 511;
                int row = i >> 3, c16 = i & 7;
                uint32_t dst = sb + A_OFF + st * A_STAGE + sel * A_MAT
                             + row * A_STRIDE + c16 * 16;
                const __nv_bfloat16* src = (sel ? g_hlo : g_hhi)
                                           + row * Hn + ck * 64 + c16 * 8;
                cpasync16(dst, src);
            }
            cp_commit();
        };

        load_stage(0, 0); load_stage(1, 1); load_stage(2, 2);

        for (int ck = 0; ck < 16; ck++) {
            const int st = ck & 3;
            if (ck + 3 < 16) load_stage((ck + 3) & 3, ck + 3);
            if (ck < 13)
                asm volatile("cp.async.wait_group 3;" ::: "memory");
            else if (ck == 13)
                asm volatile("cp.async.wait_group 2;" ::: "memory");
            else if (ck == 14)
                asm volatile("cp.async.wait_group 1;" ::: "memory");
            else
                asm volatile("cp.async.wait_group 0;" ::: "memory");
            __syncthreads();

            const uint32_t abase = sb + A_OFF + st * A_STAGE + a_lane;
#pragma unroll
            for (int kb = 0; kb < 4; kb++) {
                uint32_t ah0, ah1, ah2, ah3, al0, al1, al2, al3;
                ldsm4(ah0, ah1, ah2, ah3, abase + kb * 32);
                ldsm4(al0, al1, al2, al3, abase + A_MAT + kb * 32);
                uint32_t bkoff = (uint32_t)((ck * 4 + kb) * 32);
                uint32_t bh0, bh1, bh2, bh3, bl0, bl1, bl2, bl3;
                ldsm4(bh0, bh1, bh2, bh3, sb + b_lane + bkoff);
                ldsm4(bl0, bl1, bl2, bl3, sb + W_LO_OFF + b_lane + bkoff);
                mma16816(acc[0], ah0, ah1, ah2, ah3, bh0, bh1);
                mma16816(acc[0], ah0, ah1, ah2, ah3, bl0, bl1);
                mma16816(acc[0], al0, al1, al2, al3, bh0, bh1);
                mma16816(acc[1], ah0, ah1, ah2, ah3, bh2, bh3);
                mma16816(acc[1], ah0, ah1, ah2, ah3, bl2, bl3);
                mma16816(acc[1], al0, al1, al2, al3, bh2, bh3);
            }
        }

        // Epilogue: fragments -> gate smem [b 64][n 32] (stride GSTR, even)
        float* gsm = (float*)(smc + GSM_OFF);
        {
            int rl = mi * 16 + (lane >> 2);
#pragma unroll
            for (int nt = 0; nt < 2; nt++) {
                int c0 = nz * 16 + nt * 8 + (lane & 3) * 2;
                *(float2*)(gsm + rl * GSTR + c0)       = make_float2(acc[nt][0], acc[nt][1]);
                *(float2*)(gsm + (rl + 8) * GSTR + c0) = make_float2(acc[nt][2], acc[nt][3]);
            }
        }
        __syncthreads();

        // Pointwise: 2 cells per thread
        {
            const float* gb = gsm + pb * GSTR;
            float2 ri = *(const float2*)(gb + jj);
            float2 rf = *(const float2*)(gb + 8 + jj);
            float2 rg = *(const float2*)(gb + 16 + jj);
            float2 ro = *(const float2*)(gb + 24 + jj);

            float cc0 = (t == 0) ? 0.0f : cp0[0];
            float cc1 = (t == 0) ? 0.0f : cp0[1];

            float i0 = sigf(ri.x + qi.x), i1 = sigf(ri.y + qi.y);
            float f0 = sigf(rf.x + qf.x), f1 = sigf(rf.y + qf.y);
            float g0 = tanhf(rg.x + qg.x), g1 = tanhf(rg.y + qg.y);
            float o0 = sigf(ro.x + qo.x), o1 = sigf(ro.y + qo.y);
            cc0 = f0 * cc0 + i0 * g0;
            cc1 = f1 * cc1 + i1 * g1;
            cp0[0] = cc0; cp0[1] = cc1;
            float h0 = o0 * tanhf(cc0);
            float h1 = o1 * tanhf(cc1);

            __nv_bfloat16 h0h = __float2bfloat16(h0);
            __nv_bfloat16 h1h = __float2bfloat16(h1);
            __nv_bfloat16 h0l = __float2bfloat16(h0 - __bfloat162float(h0h));
            __nv_bfloat16 h1l = __float2bfloat16(h1 - __bfloat162float(h1h));

            int hidx = pb * Hn + j0 + jj;
            *(__nv_bfloat162*)(g_hhi + hidx) = __nv_bfloat162(h0h, h1h);
            *(__nv_bfloat162*)(g_hlo + hidx) = __nv_bfloat162(h0l, h1l);
            size_t sidx = (size_t)t * Bn * Hn + hidx;
            *(__nv_bfloat162*)(shi + sidx) = __nv_bfloat162(h0h, h1h);
            *(__nv_bfloat162*)(slo + sidx) = __nv_bfloat162(h0l, h1l);
        }

        grid_sync(phase0 + t + 1);
    }
}

// ---------------------------------------------------------------------------
// fp32 -> bf16 hi/lo split conversion (elementwise)
// ---------------------------------------------------------------------------
__global__ void cvt_split(const float* __restrict__ in,
                          __nv_bfloat16* __restrict__ hi,
                          __nv_bfloat16* __restrict__ lo, int n4)
{
    int i = blockIdx.x * blockDim.x + threadIdx.x;
    if (i >= n4) return;
    float4 v = __ldg((const float4*)in + i);
    __nv_bfloat16 h0 = __float2bfloat16(v.x);
    __nv_bfloat16 h1 = __float2bfloat16(v.y);
    __nv_bfloat16 h2 = __float2bfloat16(v.z);
    __nv_bfloat16 h3 = __float2bfloat16(v.w);
    __nv_bfloat16 l0 = __float2bfloat16(v.x - __bfloat162float(h0));
    __nv_bfloat16 l1 = __float2bfloat16(v.y - __bfloat162float(h1));
    __nv_bfloat16 l2 = __float2bfloat16(v.z - __bfloat162float(h2));
    __nv_bfloat16 l3 = __float2bfloat16(v.w - __bfloat162float(h3));
    *((__nv_bfloat162*)hi + 2*i)     = __nv_bfloat162(h0, h1);
    *((__nv_bfloat162*)hi + 2*i + 1) = __nv_bfloat162(h2, h3);
    *((__nv_bfloat162*)lo + 2*i)     = __nv_bfloat162(l0, l1);
    *((__nv_bfloat162*)lo + 2*i + 1) = __nv_bfloat162(l2, l3);
}

// ---------------------------------------------------------------------------
// HMMA bf16-split GEMM (R7-proven): C = (Ahi+Alo) @ (Whi+Wlo)^T + bias
// ---------------------------------------------------------------------------
__global__ void __launch_bounds__(256, 1)
gemm_tc(const __nv_bfloat16* __restrict__ Ahi, const __nv_bfloat16* __restrict__ Alo,
        const __nv_bfloat16* __restrict__ Whi, const __nv_bfloat16* __restrict__ Wlo,
        const float* __restrict__ b0, const float* __restrict__ b1,
        float* __restrict__ C, int K, int N)
{
    extern __shared__ char smc[];
    const uint32_t sb = smem_u32(smc);
    const int tid = threadIdx.x, lane = tid & 31, wid = tid >> 5;
    const int m0 = blockIdx.y * BM, n0 = blockIdx.x * BN;
    const int wm = (wid & 1) * 64, wn = (wid >> 1) * 32;

    float acc[4][4][4];
#pragma unroll
    for (int i = 0; i < 4; i++)
#pragma unroll
        for (int j = 0; j < 4; j++)
#pragma unroll
            for (int l = 0; l < 4; l++) acc[i][j][l] = 0.0f;

    const int r0l = tid >> 2, ch0 = (tid & 3);
    const int r1l = (tid + 256) >> 2, ch1 = ((tid + 256) & 3);
    const int NS = K / BK;

    auto load_stage = [&](int st, int ck) {
        uint32_t sbase = sb + st * STGB;
        const __nv_bfloat16* ap;
        ap = Ahi + (size_t)(m0 + r0l) * K + ck * BK + ch0 * 8;
        cpasync16(sbase + 0*MATB + r0l * ROWB + ch0 * 16, ap);
        ap = Ahi + (size_t)(m0 + r1l) * K + ck * BK + ch1 * 8;
        cpasync16(sbase + 0*MATB + r1l * ROWB + ch1 * 16, ap);
        ap = Alo + (size_t)(m0 + r0l) * K + ck * BK + ch0 * 8;
        cpasync16(sbase + 1*MATB + r0l * ROWB + ch0 * 16, ap);
        ap = Alo + (size_t)(m0 + r1l) * K + ck * BK + ch1 * 8;
        cpasync16(sbase + 1*MATB + r1l * ROWB + ch1 * 16, ap);
        ap = Whi + (size_t)(n0 + r0l) * K + ck * BK + ch0 * 8;
        cpasync16(sbase + 2*MATB + r0l * ROWB + ch0 * 16, ap);
        ap = Whi + (size_t)(n0 + r1l) * K + ck * BK + ch1 * 8;
        cpasync16(sbase + 2*MATB + r1l * ROWB + ch1 * 16, ap);
        ap = Wlo + (size_t)(n0 + r0l) * K + ck * BK + ch0 * 8;
        cpasync16(sbase + 3*MATB + r0l * ROWB + ch0 * 16, ap);
        ap = Wlo + (size_t)(n0 + r1l) * K + ck * BK + ch1 * 8;
        cpasync16(sbase + 3*MATB + r1l * ROWB + ch1 * 16, ap);
        cp_commit();
    };

    load_stage(0, 0);

    const uint32_t aoff = (uint32_t)((wm + (lane & 15)) * ROWB + (lane >> 4) * 16);
    const uint32_t boff = (uint32_t)((wn + (lane & 7) + ((lane >> 4) << 3)) * ROWB
                                     + ((lane >> 3) & 1) * 16);

    for (int ck = 0; ck < NS; ck++) {
        const int st = ck & 1;
        if (ck + 1 < NS) {
            load_stage(st ^ 1, ck + 1);
            asm volatile("cp.async.wait_group 1;" ::: "memory");
        } else {
            asm volatile("cp.async.wait_group 0;" ::: "memory");
        }
        __syncthreads();

        const uint32_t sbase = sb + st * STGB;
#pragma unroll
        for (int kk = 0; kk < 2; kk++) {
            const uint32_t ko = kk * 32;
            uint32_t bh[2][4], bl[2][4];
#pragma unroll
            for (int nb = 0; nb < 2; nb++) {
                uint32_t ba = sbase + boff + nb * (16 * ROWB) + ko;
                ldsm4(bh[nb][0], bh[nb][1], bh[nb][2], bh[nb][3], ba + 2*MATB);
                ldsm4(bl[nb][0], bl[nb][1], bl[nb][2], bl[nb][3], ba + 3*MATB);
            }
            uint32_t ah[4][4], al[4][4];
#pragma unroll
            for (int mi = 0; mi < 4; mi++) {
                uint32_t aa = sbase + aoff + mi * (16 * ROWB) + ko;
                ldsm4(ah[mi][0], ah[mi][1], ah[mi][2], ah[mi][3], aa);
                ldsm4(al[mi][0], al[mi][1], al[mi][2], al[mi][3], aa + MATB);
            }
#pragma unroll
            for (int mi = 0; mi < 4; mi++) {
#pragma unroll
                for (int ni = 0; ni < 4; ni++) {
                    const int nb = ni >> 1, pr = (ni & 1) * 2;
                    float* c = acc[mi][ni];
                    mma16816(c, ah[mi][0], ah[mi][1], ah[mi][2], ah[mi][3],
                             bh[nb][pr], bh[nb][pr + 1]);
                    mma16816(c, ah[mi][0], ah[mi][1], ah[mi][2], ah[mi][3],
                             bl[nb][pr], bl[nb][pr + 1]);
                    mma16816(c, al[mi][0], al[mi][1], al[mi][2], al[mi][3],
                             bh[nb][pr], bh[nb][pr + 1]);
                }
            }
        }
        __syncthreads();
    }

#pragma unroll
    for (int ni = 0; ni < 4; ni++) {
        int cc = n0 + wn + ni * 8 + (lane & 3) * 2;
        float bb0 = __ldg(b0 + cc) + (b1 ? __ldg(b1 + cc) : 0.0f);
        float bb1 = __ldg(b0 + cc + 1) + (b1 ? __ldg(b1 + cc + 1) : 0.0f);
#pragma unroll
        for (int mi = 0; mi < 4; mi++) {
            int rr = m0 + wm + mi * 16 + (lane >> 2);
            float* c = acc[mi][ni];
            *(float2*)(C + (size_t)rr * N + cc) =
                make_float2(c[0] + bb0, c[1] + bb1);
            *(float2*)(C + (size_t)(rr + 8) * N + cc) =
                make_float2(c[2] + bb0, c[3] + bb1);
        }
    }
}

// ---------------------------------------------------------------------------
extern "C" void kernel_launch(void* const* d_in, const int* in_sizes, int n_in,
                              void* d_out, int out_size)
{
    const float* x    = (const float*)d_in[0];
    const float* Wih0 = (const float*)d_in[1];
    const float* Whh0 = (const float*)d_in[2];
    const float* bih0 = (const float*)d_in[3];
    const float* bhh0 = (const float*)d_in[4];
    const float* Wih1 = (const float*)d_in[5];
    const float* Whh1 = (const float*)d_in[6];
    const float* bih1 = (const float*)d_in[7];
    const float* bhh1 = (const float*)d_in[8];
    const float* Wout = (const float*)d_in[9];
    const float* bout = (const float*)d_in[10];
    float* out = (float*)d_out;

    float* pre;
    __nv_bfloat16 *ahi, *alo, *whi, *wlo, *shi, *slo, *hhi, *hlo;
    cudaGetSymbolAddress((void**)&pre, g_pre);
    cudaGetSymbolAddress((void**)&ahi, g_ahi);
    cudaGetSymbolAddress((void**)&alo, g_alo);
    cudaGetSymbolAddress((void**)&whi, g_whi);
    cudaGetSymbolAddress((void**)&wlo, g_wlo);
    cudaGetSymbolAddress((void**)&shi, g_shi);
    cudaGetSymbolAddress((void**)&slo, g_slo);
    cudaGetSymbolAddress((void**)&hhi, g_hhi);
    cudaGetSymbolAddress((void**)&hlo, g_hlo);

    cudaFuncSetAttribute(lstm_recur, cudaFuncAttributeMaxDynamicSharedMemorySize,
                         SMEM_RECUR);
    cudaFuncSetAttribute(gemm_tc, cudaFuncAttributeMaxDynamicSharedMemorySize,
                         SMEM_GEMM);

    // ---- Layer 0 ----
    cvt_split<<<(TBn*In/4 + 255)/256, 256>>>(x, ahi, alo, TBn*In/4);
    cvt_split<<<(Gn*In/4 + 255)/256, 256>>>(Wih0, whi, wlo, Gn*In/4);
    gemm_tc<<<dim3(Gn/BN, TBn/BM), 256, SMEM_GEMM>>>(
        ahi, alo, whi, wlo, bih0, bhh0, pre, In, Gn);
    cudaMemsetAsync(hhi, 0, sizeof(__nv_bfloat16)*Bn*Hn);
    cudaMemsetAsync(hlo, 0, sizeof(__nv_bfloat16)*Bn*Hn);
    lstm_recur<<<NCTA, NTHR, SMEM_RECUR>>>(Whh0, pre, shi, slo);

    // ---- Layer 1 (A = hseq hi/lo directly) ----
    cvt_split<<<(Gn*Hn/4 + 255)/256, 256>>>(Wih1, whi, wlo, Gn*Hn/4);
    gemm_tc<<<dim3(Gn/BN, TBn/BM), 256, SMEM_GEMM>>>(
        shi, slo, whi, wlo, bih1, bhh1, pre, Hn, Gn);
    cudaMemsetAsync(hhi, 0, sizeof(__nv_bfloat16)*Bn*Hn);
    cudaMemsetAsync(hlo, 0, sizeof(__nv_bfloat16)*Bn*Hn);
    lstm_recur<<<NCTA, NTHR, SMEM_RECUR>>>(Whh1, pre, shi, slo);

    // ---- Output projection (A = hseq hi/lo) ----
    cvt_split<<<(On*Hn/4 + 255)/256, 256>>>(Wout, whi, wlo, On*Hn/4);
    gemm_tc<<<dim3(On/BN, TBn/BM), 256, SMEM_GEMM>>>(
        shi, slo, whi, wlo, bout, nullptr, out, Hn, On);
}